// round 16
// baseline (speedup 1.0000x reference)
#include <cuda_runtime.h>
#include <cuda_fp16.h>
#include <math.h>
#include <stdint.h>

#define VOCAB   100
#define NBOND   4
#define EMB     128
#define N_NODES 25000
#define N_EDGES 50000
#define MAX_NB  6
#define HOFF    104
#define NT      391              // ceil(50000/128) edge tiles
#define PAD_E   (NT * 128)       // 50048
#define ROWP    136              // padded row length (fp16 elems) -> 272B rows
#define PLANE_A 34816            // 128*ROWP*2 bytes, one 128-row fp16 plane
#define WELEMS  17408            // 128*ROWP elems per W plane

// ---------------- static device scratch (no allocation) ----------------
// cell state ping-pong, packed fp16: half2(c(d0), c(d0+1)) per (e, dh)
__device__ uint32_t g_ch[2][N_EDGES * (EMB / 2)];
// interleaved GEMM gate preacts: per (e, dpair): {io(d), io(d+1), uf(d), uf(d+1)} as 4x half2
__device__ uint4 g_P4[N_EDGES * (EMB / 2)];
// one-hot preact LUTs in the same packed component layout (fp16):
//   lutN[row][dh] = W rows (no bias), lutB[et][dh] = W bond rows + biases
__device__ uint4 g_lutN[VOCAB * (EMB / 2)];
__device__ uint4 g_lutB[NBOND * (EMB / 2)];
__device__ int   g_rowidx[N_EDGES];                      // nrow | (etype<<16)
__device__ float g_Ht[N_EDGES * EMB];                    // final-pass fp32 Ht
__device__ __align__(16) __half g_hb[2][PAD_E * ROWP];   // h fp16 planes (ping-pong), padded rows
__device__ __align__(16) __half g_W[5][WELEMS];          // W[k][d] fp16, padded rows

// fast activations: tanh.approx.f32 (sm_75+ baseline PTX)
__device__ __forceinline__ float tanhfast(float x) {
    float y;
    asm("tanh.approx.f32 %0, %1;" : "=f"(y) : "f"(x));
    return y;
}
__device__ __forceinline__ float sigfast(float x) {
    return fmaf(0.5f, tanhfast(0.5f * x), 0.5f);
}

__device__ __forceinline__ uint32_t smem_u32(const void* p) {
    uint32_t a;
    asm("{ .reg .u64 t; cvta.to.shared.u64 t, %1; cvt.u32.u64 %0, t; }" : "=r"(a) : "l"(p));
    return a;
}
__device__ __forceinline__ void cpa16(uint32_t s, const void* g) {
    asm volatile("cp.async.cg.shared.global [%0], [%1], 16;" :: "r"(s), "l"(g) : "memory");
}
#define CP_COMMIT() asm volatile("cp.async.commit_group;" ::: "memory")
#define CP_WAIT0()  asm volatile("cp.async.wait_group 0;" ::: "memory")

__device__ __forceinline__ void ldsm_x4(uint32_t* r, uint32_t addr) {
    asm volatile("ldmatrix.sync.aligned.m8n8.x4.shared.b16 {%0,%1,%2,%3}, [%4];"
                 : "=r"(r[0]), "=r"(r[1]), "=r"(r[2]), "=r"(r[3]) : "r"(addr));
}
__device__ __forceinline__ void ldsm_x2t(uint32_t* r, uint32_t addr) {
    asm volatile("ldmatrix.sync.aligned.m8n8.x2.trans.shared.b16 {%0,%1}, [%2];"
                 : "=r"(r[0]), "=r"(r[1]) : "r"(addr));
}
// fp16 inputs, fp32 accumulate
__device__ __forceinline__ void mma16816(float* c, const uint32_t* a, const uint32_t* b) {
    asm volatile("mma.sync.aligned.m16n8k16.row.col.f32.f16.f16.f32 "
                 "{%0,%1,%2,%3}, {%4,%5,%6,%7}, {%8,%9}, {%0,%1,%2,%3};"
                 : "+f"(c[0]), "+f"(c[1]), "+f"(c[2]), "+f"(c[3])
                 : "r"(a[0]), "r"(a[1]), "r"(a[2]), "r"(a[3]), "r"(b[0]), "r"(b[1]));
}
__device__ __forceinline__ uint32_t prmt(uint32_t a, uint32_t b, uint32_t s) {
    uint32_t d;
    asm("prmt.b32 %0, %1, %2, %3;" : "=r"(d) : "r"(a), "r"(b), "r"(s));
    return d;
}
__device__ __forceinline__ uint32_t f2h2(float a, float b) {
    __half2 h = __floats2half2_rn(a, b);   // low = a
    return *(uint32_t*)&h;
}
__device__ __forceinline__ float2 h2f2(uint32_t w) {
    return __half22float2(*(__half2*)&w);
}

// write (e, d0) and (e, d0+1) h values as one fp16x2 (4B) store
__device__ __forceinline__ void store_h2(int buf, int e, int d0, float h0, float h1) {
    *(uint32_t*)&g_hb[buf][e * ROWP + d0] = f2h2(h0, h1);
}

// ---------------------------------------------------------------------------
// Prep: W fp16 planes, rows k = 0..127 (source rows roff+k), padded to ROWP
// ---------------------------------------------------------------------------
__global__ __launch_bounds__(256) void k_prep(
    const float* __restrict__ Wi, const float* __restrict__ Wo,
    const float* __restrict__ Wu, const float* __restrict__ Wf,
    const float* __restrict__ Wt)
{
    int g = blockIdx.x;
    const float* W;
    int roff;
    switch (g) {
        case 0: W = Wi; roff = HOFF; break;
        case 1: W = Wo; roff = HOFF; break;
        case 2: W = Wu; roff = HOFF; break;
        case 3: W = Wf; roff = HOFF; break;
        default: W = Wt; roff = VOCAB; break;
    }
    for (int idx = threadIdx.x; idx < 16384; idx += 256) {
        int k = idx >> 7;
        int d = idx & 127;
        g_W[g][k * ROWP + d] = __float2half_rn(W[(roff + k) * EMB + d]);
    }
}

// ---------------------------------------------------------------------------
// LUT build: packed one-hot preact rows. 104*64 = 6656 entries.
//   row < 100 -> g_lutN[row][dh] = {io,io,uf,uf}(W[row])          (no bias)
//   row >= 100 -> g_lutB[row-100][dh] = {io,io,uf,uf}(W[row] + b) (bias folded)
// ---------------------------------------------------------------------------
__global__ __launch_bounds__(256) void k_lut(
    const float* __restrict__ Wi, const float* __restrict__ bi,
    const float* __restrict__ Wo, const float* __restrict__ bo,
    const float* __restrict__ Wu, const float* __restrict__ bu,
    const float* __restrict__ Wf, const float* __restrict__ bf)
{
    int idx = blockIdx.x * blockDim.x + threadIdx.x;
    if (idx >= (VOCAB + NBOND) * 64) return;
    int row = idx >> 6;
    int dh  = idx & 63;
    int d0  = dh * 2;

    float2 wi = *(const float2*)&Wi[row * EMB + d0];
    float2 wo = *(const float2*)&Wo[row * EMB + d0];
    float2 wu = *(const float2*)&Wu[row * EMB + d0];
    float2 wf = *(const float2*)&Wf[row * EMB + d0];

    if (row >= VOCAB) {
        float2 b1 = *(const float2*)&bi[d0];
        float2 b2 = *(const float2*)&bo[d0];
        float2 b3 = *(const float2*)&bu[d0];
        float2 b4 = *(const float2*)&bf[d0];
        wi.x += b1.x; wi.y += b1.y;
        wo.x += b2.x; wo.y += b2.y;
        wu.x += b3.x; wu.y += b3.y;
        wf.x += b4.x; wf.y += b4.y;
    }

    uint4 v;
    v.x = f2h2(wi.x, wo.x);
    v.y = f2h2(wi.y, wo.y);
    v.z = f2h2(wu.x, wf.x);
    v.w = f2h2(wu.y, wf.y);
    if (row < VOCAB) g_lutN[row * 64 + dh] = v;
    else             g_lutB[(row - VOCAB) * 64 + dh] = v;
}

// ---------------------------------------------------------------------------
// Depth 0 + rowidx precompute. fp32-accurate one-hot math for the depth-0 step.
// ---------------------------------------------------------------------------
__global__ __launch_bounds__(256) void k_pre0(
    const int* __restrict__ node_ids, const int* __restrict__ edge_src,
    const int* __restrict__ edge_type,
    const float* __restrict__ Wi, const float* __restrict__ bi,
    const float* __restrict__ Wo, const float* __restrict__ bo,
    const float* __restrict__ Wu, const float* __restrict__ bu)
{
    int gidx = blockIdx.x * blockDim.x + threadIdx.x;   // e*64 + dh
    int e = gidx >> 6, dh = gidx & 63;
    int d0 = dh * 2;
    int et = edge_type[e];
    int nrow = node_ids[edge_src[e]];
    int brow = VOCAB + et;

    if (dh == 0) g_rowidx[e] = nrow | (et << 16);

    float2 win = *(const float2*)&Wi[nrow * EMB + d0];
    float2 wib = *(const float2*)&Wi[brow * EMB + d0];
    float2 bi2 = *(const float2*)&bi[d0];
    float2 won = *(const float2*)&Wo[nrow * EMB + d0];
    float2 wob = *(const float2*)&Wo[brow * EMB + d0];
    float2 bo2 = *(const float2*)&bo[d0];
    float2 wun = *(const float2*)&Wu[nrow * EMB + d0];
    float2 wub = *(const float2*)&Wu[brow * EMB + d0];
    float2 bu2 = *(const float2*)&bu[d0];

    float h[2], c[2];
    #pragma unroll
    for (int q = 0; q < 2; q++) {
        float pi = (q ? win.y + wib.y + bi2.y : win.x + wib.x + bi2.x);
        float po = (q ? won.y + wob.y + bo2.y : won.x + wob.x + bo2.x);
        float pu = (q ? wun.y + wub.y + bu2.y : wun.x + wub.x + bu2.x);
        float i = sigfast(pi), o = sigfast(po), u = tanhfast(pu);
        c[q] = i * u;
        h[q] = o * tanhfast(c[q]);
        if (e == 0) { h[q] = 0.0f; c[q] = 0.0f; }
    }
    g_ch[0][e * 64 + dh] = f2h2(c[0], c[1]);
    store_h2(0, e, d0, h[0], h[1]);
}

// ---------------------------------------------------------------------------
// Tensor-core GEMM via mma.sync fp16 (single term, fp32 accum).
// Gate passes (gbase=0, ngates=4): gates in pairs; even gate held as packed
// halves, merged with the odd gate via prmt into g_P4 components.
// Final pass (gbase=4, ngates=1): fp32 into g_Ht.
// SMEM: A 34KB + 2 W buffers 68KB = 102KB -> 2 CTAs/SM.
// ---------------------------------------------------------------------------
#define MMA_SMEM (3 * PLANE_A)   // 104448 B

__global__ __launch_bounds__(256) void k_mma(int cur, int gbase, int ngates)
{
    extern __shared__ __align__(16) char sm[];
    const int tid  = threadIdx.x;
    const int lane = tid & 31;
    const int wid  = tid >> 5;
    const int wm   = wid >> 2;     // 0..1  -> edge offset wm*64
    const int wn   = wid & 3;      // 0..3  -> dim  offset wn*32
    const int tile = blockIdx.x;

    const uint32_t sA  = smem_u32(sm);
    const uint32_t sB0 = sA + PLANE_A;
    const uint32_t sB1 = sA + 2 * PLANE_A;

    // stage A (h tile) + first W via cp.async
    {
        const uint4* gA = (const uint4*)&g_hb[cur][(size_t)tile * 128 * ROWP];
        const uint4* gW0 = (const uint4*)&g_W[gbase][0];
        for (int i = tid; i < 2176; i += 256) cpa16(sA + i * 16, gA + i);
        for (int i = tid; i < 2176; i += 256) cpa16(sB0 + i * 16, gW0 + i);
        CP_COMMIT();
        CP_WAIT0();
    }
    __syncthreads();

    // per-thread ldmatrix base addresses
    const uint32_t aBase = sA + (uint32_t)((wm * 64 + (lane & 15)) * ROWP + ((lane & 16) ? 8 : 0)) * 2;
    const uint32_t bRow  = (uint32_t)((lane & 15) * ROWP + wn * 32) * 2;

    uint32_t hold[32];   // even gate's halves: per (mf,nf): [d0,d0+1]@e0, [d0,d0+1]@e0+8

    for (int g = 0; g < ngates; g++) {
        // prefetch next gate's W into the other buffer
        if (g + 1 < ngates) {
            const uint4* gw = (const uint4*)&g_W[gbase + g + 1][0];
            uint32_t dst = ((g + 1) & 1) ? sB1 : sB0;
            for (int i = tid; i < 2176; i += 256) cpa16(dst + i * 16, gw + i);
            CP_COMMIT();
        }

        float acc[4][4][4];
        #pragma unroll
        for (int mf = 0; mf < 4; mf++)
            #pragma unroll
            for (int nf = 0; nf < 4; nf++)
                #pragma unroll
                for (int q = 0; q < 4; q++) acc[mf][nf][q] = 0.f;

        const uint32_t sB = ((g & 1) ? sB1 : sB0) + bRow;

        #pragma unroll
        for (int ks = 0; ks < 8; ks++) {
            uint32_t aK = aBase + ks * 32;           // +16 cols * 2B
            uint32_t bK = sB + ks * (16 * ROWP * 2); // +16 k-rows
            uint32_t afr[4][4];
            #pragma unroll
            for (int mf = 0; mf < 4; mf++)
                ldsm_x4(afr[mf], aK + mf * (16 * ROWP * 2));
            uint32_t bfr[4][2];
            #pragma unroll
            for (int nf = 0; nf < 4; nf++)
                ldsm_x2t(bfr[nf], bK + nf * 16);
            #pragma unroll
            for (int mf = 0; mf < 4; mf++)
                #pragma unroll
                for (int nf = 0; nf < 4; nf++)
                    mma16816(acc[mf][nf], afr[mf], bfr[nf]);
        }

        // epilogue
        if (gbase == 4) {
            float* __restrict__ H = g_Ht;
            #pragma unroll
            for (int mf = 0; mf < 4; mf++) {
                int e0 = tile * 128 + wm * 64 + mf * 16 + (lane >> 2);
                #pragma unroll
                for (int nf = 0; nf < 4; nf++) {
                    int d0 = wn * 32 + nf * 8 + (lane & 3) * 2;
                    if (e0 < N_EDGES)
                        *(float2*)&H[e0 * EMB + d0] = make_float2(acc[mf][nf][0], acc[mf][nf][1]);
                    if (e0 + 8 < N_EDGES)
                        *(float2*)&H[(e0 + 8) * EMB + d0] = make_float2(acc[mf][nf][2], acc[mf][nf][3]);
                }
            }
        } else if ((g & 1) == 0) {
            // even gate: pack and hold
            #pragma unroll
            for (int mf = 0; mf < 4; mf++)
                #pragma unroll
                for (int nf = 0; nf < 4; nf++) {
                    hold[(mf * 4 + nf) * 2 + 0] = f2h2(acc[mf][nf][0], acc[mf][nf][1]);
                    hold[(mf * 4 + nf) * 2 + 1] = f2h2(acc[mf][nf][2], acc[mf][nf][3]);
                }
        } else {
            // odd gate: merge with held even gate; pair (0,1)->.xy, (2,3)->.zw
            const int zoff = (g & 2) ? 2 : 0;   // uint offset within uint4 word
            uint32_t* __restrict__ P = (uint32_t*)g_P4;
            #pragma unroll
            for (int mf = 0; mf < 4; mf++) {
                int e0 = tile * 128 + wm * 64 + mf * 16 + (lane >> 2);
                #pragma unroll
                for (int nf = 0; nf < 4; nf++) {
                    int d0 = wn * 32 + nf * 8 + (lane & 3) * 2;
                    uint32_t ev0 = hold[(mf * 4 + nf) * 2 + 0];
                    uint32_t ev1 = hold[(mf * 4 + nf) * 2 + 1];
                    uint32_t od0 = f2h2(acc[mf][nf][0], acc[mf][nf][1]);
                    uint32_t od1 = f2h2(acc[mf][nf][2], acc[mf][nf][3]);
                    if (e0 < N_EDGES) {
                        uint2 w = make_uint2(prmt(ev0, od0, 0x5410), prmt(ev0, od0, 0x7632));
                        *(uint2*)&P[(e0 * 64 + (d0 >> 1)) * 4 + zoff] = w;
                    }
                    if (e0 + 8 < N_EDGES) {
                        uint2 w = make_uint2(prmt(ev1, od1, 0x5410), prmt(ev1, od1, 0x7632));
                        *(uint2*)&P[((e0 + 8) * 64 + (d0 >> 1)) * 4 + zoff] = w;
                    }
                }
            }
        }

        if (g + 1 < ngates) {
            CP_WAIT0();
            __syncthreads();   // next buffer ready; all warps done reading current
        }
    }
}

// ---------------------------------------------------------------------------
// Update: 6x16B P4 gathers + 6x4B fp16 c gathers + 2 LUT loads (L1-hot).
// 4 edges per 256-thread block; 64 threads x 2 dims per edge.
// ---------------------------------------------------------------------------
__global__ __launch_bounds__(256) void k_update(
    int cur, int nxt, const int* __restrict__ bond_list)
{
    __shared__ int s_b[4 * MAX_NB];
    __shared__ int s_ri[4];

    const uint4* __restrict__ P4 = g_P4;
    const uint32_t* __restrict__ c_old = g_ch[cur];
    uint32_t* __restrict__ c_new = g_ch[nxt];

    const int tid = threadIdx.x;
    const int e0  = blockIdx.x * 4;

    if (tid < 4 * MAX_NB) {
        s_b[tid] = bond_list[e0 * MAX_NB + tid];
    } else if (tid < 4 * MAX_NB + 4) {
        int e = tid - 4 * MAX_NB;
        s_ri[e] = g_rowidx[e0 + e];
    }
    __syncthreads();

    const int le = tid >> 6;        // local edge 0..3
    const int dh = tid & 63;        // dim pair index
    const int d0 = dh * 2;
    const int e  = e0 + le;

    int b[MAX_NB];
    #pragma unroll
    for (int k = 0; k < MAX_NB; k++) b[k] = s_b[le * MAX_NB + k];

    // batched independent gathers: 6x16B + 6x4B + 2 LUT 16B (hot)
    uint4    p[MAX_NB];
    uint32_t cw[MAX_NB];
    #pragma unroll
    for (int k = 0; k < MAX_NB; k++) {
        p[k]  = P4[b[k] * 64 + dh];
        cw[k] = c_old[b[k] * 64 + dh];
    }
    const int ri = s_ri[le];
    uint4 lN = g_lutN[(ri & 0xFFFF) * 64 + dh];
    uint4 lB = g_lutB[(ri >> 16) * 64 + dh];

    float si[2] = {0.f, 0.f}, so[2] = {0.f, 0.f}, su[2] = {0.f, 0.f};
    float vf[2][MAX_NB];
    float2 vc[MAX_NB];
    #pragma unroll
    for (int k = 0; k < MAX_NB; k++) {
        float2 io0 = h2f2(p[k].x);   // (i,o)@d0
        float2 io1 = h2f2(p[k].y);   // (i,o)@d0+1
        float2 uf0 = h2f2(p[k].z);   // (u,f)@d0
        float2 uf1 = h2f2(p[k].w);   // (u,f)@d0+1
        si[0] += io0.x; so[0] += io0.y; su[0] += uf0.x; vf[0][k] = uf0.y;
        si[1] += io1.x; so[1] += io1.y; su[1] += uf1.x; vf[1][k] = uf1.y;
        vc[k] = h2f2(cw[k]);         // (c(d0), c(d0+1))
    }

    // one-hot preacts from LUTs: pre = lutN + lutB (biases in lutB)
    float2 nio0 = h2f2(lN.x), bio0 = h2f2(lB.x);
    float2 nio1 = h2f2(lN.y), bio1 = h2f2(lB.y);
    float2 nuf0 = h2f2(lN.z), buf0 = h2f2(lB.z);
    float2 nuf1 = h2f2(lN.w), buf1 = h2f2(lB.w);
    float2 pio0 = make_float2(nio0.x + bio0.x, nio0.y + bio0.y);
    float2 pio1 = make_float2(nio1.x + bio1.x, nio1.y + bio1.y);
    float2 puf0 = make_float2(nuf0.x + buf0.x, nuf0.y + buf0.y);
    float2 puf1 = make_float2(nuf1.x + buf1.x, nuf1.y + buf1.y);

    float h[2], c[2];
    #pragma unroll
    for (int q = 0; q < 2; q++) {
        float pi = q ? pio1.x : pio0.x;
        float po = q ? pio1.y : pio0.y;
        float pu = q ? puf1.x : puf0.x;
        float pf = q ? puf1.y : puf0.y;

        float i_g = sigfast(si[q] + pi);
        float o_g = sigfast(so[q] + po);
        float u_g = tanhfast(su[q] + pu);

        float c_acc = i_g * u_g;
        #pragma unroll
        for (int k = 0; k < MAX_NB; k++)
            c_acc += sigfast(vf[q][k] + pf) * (q ? vc[k].y : vc[k].x);

        h[q] = o_g * tanhfast(c_acc);
        c[q] = c_acc;
        if (e == 0) { h[q] = 0.f; c[q] = 0.f; }
    }

    c_new[e * 64 + dh] = f2h2(c[0], c[1]);
    store_h2(nxt, e, d0, h[0], h[1]);
}

// ---------------------------------------------------------------------------
// Final node projection: out = relu(Wt[nid] + bt + sum_k Ht[adj[n,k]])
// ---------------------------------------------------------------------------
__global__ __launch_bounds__(256) void k_final(
    const int* __restrict__ node_ids, const int* __restrict__ adj_list,
    const float* __restrict__ Wt, const float* __restrict__ bt,
    float* __restrict__ out)
{
    __shared__ int s_a[2 * MAX_NB];
    __shared__ int s_nid[2];

    const float* __restrict__ Ht = g_Ht;

    const int tid = threadIdx.x;
    const int n0  = blockIdx.x * 2;

    if (tid < 2 * MAX_NB) {
        s_a[tid] = adj_list[n0 * MAX_NB + tid];
    } else if (tid < 2 * MAX_NB + 2) {
        int n = tid - 2 * MAX_NB;
        s_nid[n] = node_ids[n0 + n];
    }
    __syncthreads();

    const int ln = tid >> 7;
    const int d  = tid & 127;
    const int n  = n0 + ln;

    float s = 0.f;
    #pragma unroll
    for (int k = 0; k < MAX_NB; k++)
        s += Ht[s_a[ln * MAX_NB + k] * EMB + d];

    float v = s + Wt[s_nid[ln] * EMB + d] + bt[d];
    v = fmaxf(v, 0.f);
    if (n == 0) v = 0.f;
    out[n * EMB + d] = v;
}

// ---------------------------------------------------------------------------
extern "C" void kernel_launch(void* const* d_in, const int* in_sizes, int n_in,
                              void* d_out, int out_size)
{
    const int*   node_ids  = (const int*)d_in[0];
    const int*   edge_src  = (const int*)d_in[1];
    const int*   edge_type = (const int*)d_in[2];
    const int*   adj_list  = (const int*)d_in[3];
    const int*   bond_list = (const int*)d_in[4];
    const float* Wi = (const float*)d_in[5];
    const float* bi = (const float*)d_in[6];
    const float* Wo = (const float*)d_in[7];
    const float* bo = (const float*)d_in[8];
    const float* Wf = (const float*)d_in[9];
    const float* bf = (const float*)d_in[10];
    const float* Wu = (const float*)d_in[11];
    const float* bu = (const float*)d_in[12];
    const float* Wt = (const float*)d_in[13];
    const float* bt = (const float*)d_in[14];
    float* out = (float*)d_out;

    cudaFuncSetAttribute(k_mma, cudaFuncAttributeMaxDynamicSharedMemorySize, MMA_SMEM);

    k_prep<<<5, 256>>>(Wi, Wo, Wu, Wf, Wt);
    k_lut<<<26, 256>>>(Wi, bi, Wo, bo, Wu, bu, Wf, bf);
    k_pre0<<<(N_EDGES * 64) / 256, 256>>>(node_ids, edge_src, edge_type,
                                          Wi, bi, Wo, bo, Wu, bu);

    int cur = 0, nxt = 1;
    for (int depth = 1; depth < 4; depth++) {
        k_mma<<<NT, 256, MMA_SMEM>>>(cur, 0, 4);
        k_update<<<N_EDGES / 4, 256>>>(cur, nxt, bond_list);
        int t = cur; cur = nxt; nxt = t;
    }

    k_mma<<<NT, 256, MMA_SMEM>>>(cur, 4, 1);   // Ht -> g_Ht (fp32)
    k_final<<<N_NODES / 2, 256>>>(node_ids, adj_list, Wt, bt, out);
}

// round 17
// speedup vs baseline: 1.0580x; 1.0580x over previous
#include <cuda_runtime.h>
#include <cuda_fp16.h>
#include <math.h>
#include <stdint.h>

#define VOCAB   100
#define NBOND   4
#define EMB     128
#define N_NODES 25000
#define N_EDGES 50000
#define MAX_NB  6
#define HOFF    104
#define NT      391              // ceil(50000/128) edge tiles
#define PAD_E   (NT * 128)       // 50048
#define ROWP    136              // padded row length (fp16 elems) -> 272B rows
#define PLANE_A 34816            // 128*ROWP*2 bytes, one 128-row fp16 plane
#define WELEMS  17408            // 128*ROWP elems per W plane

// ---------------- static device scratch (no allocation) ----------------
// cell state ping-pong, packed fp16: half2(c(d0), c(d0+1)) per (e, dh)
__device__ uint32_t g_ch[2][N_EDGES * (EMB / 2)];
// interleaved GEMM gate preacts: per (e, dpair): {io(d), io(d+1), uf(d), uf(d+1)} as 4x half2
__device__ uint4 g_P4[N_EDGES * (EMB / 2)];
// depth-invariant one-hot preacts (incl. biases), same component layout as g_P4
__device__ uint4 g_pre4[N_EDGES * (EMB / 2)];
__device__ float g_Ht[N_EDGES * EMB];                    // final-pass fp32 Ht
__device__ __align__(16) __half g_hb[2][PAD_E * ROWP];   // h fp16 planes (ping-pong), padded rows
__device__ __align__(16) __half g_W[5][WELEMS];          // W[k][d] fp16, padded rows

// fast activations: tanh.approx.f32 (sm_75+ baseline PTX)
__device__ __forceinline__ float tanhfast(float x) {
    float y;
    asm("tanh.approx.f32 %0, %1;" : "=f"(y) : "f"(x));
    return y;
}
__device__ __forceinline__ float sigfast(float x) {
    return fmaf(0.5f, tanhfast(0.5f * x), 0.5f);
}

__device__ __forceinline__ uint32_t smem_u32(const void* p) {
    uint32_t a;
    asm("{ .reg .u64 t; cvta.to.shared.u64 t, %1; cvt.u32.u64 %0, t; }" : "=r"(a) : "l"(p));
    return a;
}
__device__ __forceinline__ void cpa16(uint32_t s, const void* g) {
    asm volatile("cp.async.cg.shared.global [%0], [%1], 16;" :: "r"(s), "l"(g) : "memory");
}
#define CP_COMMIT() asm volatile("cp.async.commit_group;" ::: "memory")
#define CP_WAIT0()  asm volatile("cp.async.wait_group 0;" ::: "memory")

__device__ __forceinline__ void ldsm_x4(uint32_t* r, uint32_t addr) {
    asm volatile("ldmatrix.sync.aligned.m8n8.x4.shared.b16 {%0,%1,%2,%3}, [%4];"
                 : "=r"(r[0]), "=r"(r[1]), "=r"(r[2]), "=r"(r[3]) : "r"(addr));
}
__device__ __forceinline__ void ldsm_x2t(uint32_t* r, uint32_t addr) {
    asm volatile("ldmatrix.sync.aligned.m8n8.x2.trans.shared.b16 {%0,%1}, [%2];"
                 : "=r"(r[0]), "=r"(r[1]) : "r"(addr));
}
// fp16 inputs, fp32 accumulate
__device__ __forceinline__ void mma16816(float* c, const uint32_t* a, const uint32_t* b) {
    asm volatile("mma.sync.aligned.m16n8k16.row.col.f32.f16.f16.f32 "
                 "{%0,%1,%2,%3}, {%4,%5,%6,%7}, {%8,%9}, {%0,%1,%2,%3};"
                 : "+f"(c[0]), "+f"(c[1]), "+f"(c[2]), "+f"(c[3])
                 : "r"(a[0]), "r"(a[1]), "r"(a[2]), "r"(a[3]), "r"(b[0]), "r"(b[1]));
}
__device__ __forceinline__ uint32_t prmt(uint32_t a, uint32_t b, uint32_t s) {
    uint32_t d;
    asm("prmt.b32 %0, %1, %2, %3;" : "=r"(d) : "r"(a), "r"(b), "r"(s));
    return d;
}
__device__ __forceinline__ uint32_t f2h2(float a, float b) {
    __half2 h = __floats2half2_rn(a, b);   // low = a
    return *(uint32_t*)&h;
}
__device__ __forceinline__ float2 h2f2(uint32_t w) {
    return __half22float2(*(__half2*)&w);
}

// write (e, d0) and (e, d0+1) h values as one fp16x2 (4B) streaming store
// (h is consumed exactly once, linearly, by the next k_mma -> evict-first)
__device__ __forceinline__ void store_h2(int buf, int e, int d0, float h0, float h1) {
    __stcs((uint32_t*)&g_hb[buf][e * ROWP + d0], f2h2(h0, h1));
}

// ---------------------------------------------------------------------------
// Prep: W fp16 planes, rows k = 0..127 (source rows roff+k), padded to ROWP
// ---------------------------------------------------------------------------
__global__ __launch_bounds__(256) void k_prep(
    const float* __restrict__ Wi, const float* __restrict__ Wo,
    const float* __restrict__ Wu, const float* __restrict__ Wf,
    const float* __restrict__ Wt)
{
    int g = blockIdx.x;
    const float* W;
    int roff;
    switch (g) {
        case 0: W = Wi; roff = HOFF; break;
        case 1: W = Wo; roff = HOFF; break;
        case 2: W = Wu; roff = HOFF; break;
        case 3: W = Wf; roff = HOFF; break;
        default: W = Wt; roff = VOCAB; break;
    }
    for (int idx = threadIdx.x; idx < 16384; idx += 256) {
        int k = idx >> 7;
        int d = idx & 127;
        g_W[g][k * ROWP + d] = __float2half_rn(W[(roff + k) * EMB + d]);
    }
}

// ---------------------------------------------------------------------------
// Depth 0 + precompute: builds depth-invariant one-hot preacts (biases folded)
// for all 4 gates into g_pre4, AND runs the depth-0 update (h=c=0 entering).
// ---------------------------------------------------------------------------
__global__ __launch_bounds__(256) void k_pre0(
    const int* __restrict__ node_ids, const int* __restrict__ edge_src,
    const int* __restrict__ edge_type,
    const float* __restrict__ Wi, const float* __restrict__ bi,
    const float* __restrict__ Wo, const float* __restrict__ bo,
    const float* __restrict__ Wu, const float* __restrict__ bu,
    const float* __restrict__ Wf, const float* __restrict__ bf)
{
    int gidx = blockIdx.x * blockDim.x + threadIdx.x;   // e*64 + dh
    int e = gidx >> 6, dh = gidx & 63;
    int d0 = dh * 2;
    int nrow = node_ids[edge_src[e]];
    int brow = VOCAB + edge_type[e];

    float2 win = *(const float2*)&Wi[nrow * EMB + d0];
    float2 wib = *(const float2*)&Wi[brow * EMB + d0];
    float2 bi2 = *(const float2*)&bi[d0];
    float2 won = *(const float2*)&Wo[nrow * EMB + d0];
    float2 wob = *(const float2*)&Wo[brow * EMB + d0];
    float2 bo2 = *(const float2*)&bo[d0];
    float2 wun = *(const float2*)&Wu[nrow * EMB + d0];
    float2 wub = *(const float2*)&Wu[brow * EMB + d0];
    float2 bu2 = *(const float2*)&bu[d0];
    float2 wfn = *(const float2*)&Wf[nrow * EMB + d0];
    float2 wfb = *(const float2*)&Wf[brow * EMB + d0];
    float2 bf2 = *(const float2*)&bf[d0];

    float pi[2], po[2], pu[2], pf[2];
    pi[0] = win.x + wib.x + bi2.x;  pi[1] = win.y + wib.y + bi2.y;
    po[0] = won.x + wob.x + bo2.x;  po[1] = won.y + wob.y + bo2.y;
    pu[0] = wun.x + wub.x + bu2.x;  pu[1] = wun.y + wub.y + bu2.y;
    pf[0] = wfn.x + wfb.x + bf2.x;  pf[1] = wfn.y + wfb.y + bf2.y;

    // pack depth-invariant preacts: {io(d0), io(d1), uf(d0), uf(d1)}
    uint4 pre;
    pre.x = f2h2(pi[0], po[0]);
    pre.y = f2h2(pi[1], po[1]);
    pre.z = f2h2(pu[0], pf[0]);
    pre.w = f2h2(pu[1], pf[1]);
    g_pre4[e * 64 + dh] = pre;

    // depth-0 update (neighbor sums are zero)
    float h[2], c[2];
    #pragma unroll
    for (int q = 0; q < 2; q++) {
        float i = sigfast(pi[q]), o = sigfast(po[q]), u = tanhfast(pu[q]);
        c[q] = i * u;
        h[q] = o * tanhfast(c[q]);
        if (e == 0) { h[q] = 0.0f; c[q] = 0.0f; }
    }
    g_ch[0][e * 64 + dh] = f2h2(c[0], c[1]);
    store_h2(0, e, d0, h[0], h[1]);
}

// ---------------------------------------------------------------------------
// Tensor-core GEMM via mma.sync fp16 (single term, fp32 accum).
// Gate passes: grid (NT, 2), ngates=2 per CTA -> gb = y*2 handles (0,1)/(2,3).
// Even gate held as packed halves, merged with odd gate via prmt into g_P4.
// Final pass: grid (NT, 1), gbase=4, ngates=1 -> fp32 into g_Ht.
// SMEM: A 34KB + 2 W buffers 68KB = 102KB -> 2 CTAs/SM.
// ---------------------------------------------------------------------------
#define MMA_SMEM (3 * PLANE_A)   // 104448 B

__global__ __launch_bounds__(256) void k_mma(int cur, int gbase, int ngates)
{
    extern __shared__ __align__(16) char sm[];
    const int tid  = threadIdx.x;
    const int lane = tid & 31;
    const int wid  = tid >> 5;
    const int wm   = wid >> 2;     // 0..1  -> edge offset wm*64
    const int wn   = wid & 3;      // 0..3  -> dim  offset wn*32
    const int tile = blockIdx.x;
    const int gb   = gbase + blockIdx.y * ngates;   // first absolute gate for this CTA

    const uint32_t sA  = smem_u32(sm);
    const uint32_t sB0 = sA + PLANE_A;
    const uint32_t sB1 = sA + 2 * PLANE_A;

    // stage A (h tile) + first W via cp.async
    {
        const uint4* gA = (const uint4*)&g_hb[cur][(size_t)tile * 128 * ROWP];
        const uint4* gW0 = (const uint4*)&g_W[gb][0];
        for (int i = tid; i < 2176; i += 256) cpa16(sA + i * 16, gA + i);
        for (int i = tid; i < 2176; i += 256) cpa16(sB0 + i * 16, gW0 + i);
        CP_COMMIT();
        CP_WAIT0();
    }
    __syncthreads();

    // per-thread ldmatrix base addresses
    const uint32_t aBase = sA + (uint32_t)((wm * 64 + (lane & 15)) * ROWP + ((lane & 16) ? 8 : 0)) * 2;
    const uint32_t bRow  = (uint32_t)((lane & 15) * ROWP + wn * 32) * 2;

    uint32_t hold[32];   // even gate's halves: per (mf,nf): [d0,d0+1]@e0, [d0,d0+1]@e0+8

    for (int g = 0; g < ngates; g++) {
        // prefetch next gate's W into the other buffer
        if (g + 1 < ngates) {
            const uint4* gw = (const uint4*)&g_W[gb + g + 1][0];
            uint32_t dst = ((g + 1) & 1) ? sB1 : sB0;
            for (int i = tid; i < 2176; i += 256) cpa16(dst + i * 16, gw + i);
            CP_COMMIT();
        }

        float acc[4][4][4];
        #pragma unroll
        for (int mf = 0; mf < 4; mf++)
            #pragma unroll
            for (int nf = 0; nf < 4; nf++)
                #pragma unroll
                for (int q = 0; q < 4; q++) acc[mf][nf][q] = 0.f;

        const uint32_t sB = ((g & 1) ? sB1 : sB0) + bRow;

        #pragma unroll
        for (int ks = 0; ks < 8; ks++) {
            uint32_t aK = aBase + ks * 32;           // +16 cols * 2B
            uint32_t bK = sB + ks * (16 * ROWP * 2); // +16 k-rows
            uint32_t afr[4][4];
            #pragma unroll
            for (int mf = 0; mf < 4; mf++)
                ldsm_x4(afr[mf], aK + mf * (16 * ROWP * 2));
            uint32_t bfr[4][2];
            #pragma unroll
            for (int nf = 0; nf < 4; nf++)
                ldsm_x2t(bfr[nf], bK + nf * 16);
            #pragma unroll
            for (int mf = 0; mf < 4; mf++)
                #pragma unroll
                for (int nf = 0; nf < 4; nf++)
                    mma16816(acc[mf][nf], afr[mf], bfr[nf]);
        }

        // epilogue
        if (gb == 4) {
            float* __restrict__ H = g_Ht;
            #pragma unroll
            for (int mf = 0; mf < 4; mf++) {
                int e0 = tile * 128 + wm * 64 + mf * 16 + (lane >> 2);
                #pragma unroll
                for (int nf = 0; nf < 4; nf++) {
                    int d0 = wn * 32 + nf * 8 + (lane & 3) * 2;
                    if (e0 < N_EDGES)
                        *(float2*)&H[e0 * EMB + d0] = make_float2(acc[mf][nf][0], acc[mf][nf][1]);
                    if (e0 + 8 < N_EDGES)
                        *(float2*)&H[(e0 + 8) * EMB + d0] = make_float2(acc[mf][nf][2], acc[mf][nf][3]);
                }
            }
        } else if ((g & 1) == 0) {
            // even gate: pack and hold
            #pragma unroll
            for (int mf = 0; mf < 4; mf++)
                #pragma unroll
                for (int nf = 0; nf < 4; nf++) {
                    hold[(mf * 4 + nf) * 2 + 0] = f2h2(acc[mf][nf][0], acc[mf][nf][1]);
                    hold[(mf * 4 + nf) * 2 + 1] = f2h2(acc[mf][nf][2], acc[mf][nf][3]);
                }
        } else {
            // odd gate: merge with held even gate; pair (0,1)->.xy, (2,3)->.zw
            const int zoff = ((gb + g) & 2) ? 2 : 0;   // uint offset within uint4 word
            uint32_t* __restrict__ P = (uint32_t*)g_P4;
            #pragma unroll
            for (int mf = 0; mf < 4; mf++) {
                int e0 = tile * 128 + wm * 64 + mf * 16 + (lane >> 2);
                #pragma unroll
                for (int nf = 0; nf < 4; nf++) {
                    int d0 = wn * 32 + nf * 8 + (lane & 3) * 2;
                    uint32_t ev0 = hold[(mf * 4 + nf) * 2 + 0];
                    uint32_t ev1 = hold[(mf * 4 + nf) * 2 + 1];
                    uint32_t od0 = f2h2(acc[mf][nf][0], acc[mf][nf][1]);
                    uint32_t od1 = f2h2(acc[mf][nf][2], acc[mf][nf][3]);
                    if (e0 < N_EDGES) {
                        uint2 w = make_uint2(prmt(ev0, od0, 0x5410), prmt(ev0, od0, 0x7632));
                        *(uint2*)&P[(e0 * 64 + (d0 >> 1)) * 4 + zoff] = w;
                    }
                    if (e0 + 8 < N_EDGES) {
                        uint2 w = make_uint2(prmt(ev1, od1, 0x5410), prmt(ev1, od1, 0x7632));
                        *(uint2*)&P[((e0 + 8) * 64 + (d0 >> 1)) * 4 + zoff] = w;
                    }
                }
            }
        }

        if (g + 1 < ngates) {
            CP_WAIT0();
            __syncthreads();   // next buffer ready; all warps done reading current
        }
    }
}

// ---------------------------------------------------------------------------
// Update: 6x16B P4 gathers + 6x4B fp16 c gathers + ONE streamed 16B pre load.
// 4 edges per 256-thread block; 64 threads x 2 dims per edge.
// ---------------------------------------------------------------------------
__global__ __launch_bounds__(256) void k_update(
    int cur, int nxt, const int* __restrict__ bond_list)
{
    __shared__ int s_b[4 * MAX_NB];

    const uint4* __restrict__ P4 = g_P4;
    const uint32_t* __restrict__ c_old = g_ch[cur];
    uint32_t* __restrict__ c_new = g_ch[nxt];

    const int tid = threadIdx.x;
    const int e0  = blockIdx.x * 4;

    if (tid < 4 * MAX_NB)
        s_b[tid] = bond_list[e0 * MAX_NB + tid];
    __syncthreads();

    const int le = tid >> 6;        // local edge 0..3
    const int dh = tid & 63;        // dim pair index
    const int d0 = dh * 2;
    const int e  = e0 + le;

    int b[MAX_NB];
    #pragma unroll
    for (int k = 0; k < MAX_NB; k++) b[k] = s_b[le * MAX_NB + k];

    // batched independent gathers: 6x16B + 6x4B, plus one streamed pre load
    uint4    p[MAX_NB];
    uint32_t cw[MAX_NB];
    #pragma unroll
    for (int k = 0; k < MAX_NB; k++) {
        p[k]  = P4[b[k] * 64 + dh];
        cw[k] = c_old[b[k] * 64 + dh];
    }
    uint4 pre = __ldcs(&g_pre4[e * 64 + dh]);   // evict-first: protect gather set

    float si[2] = {0.f, 0.f}, so[2] = {0.f, 0.f}, su[2] = {0.f, 0.f};
    float vf[2][MAX_NB];
    float2 vc[MAX_NB];
    #pragma unroll
    for (int k = 0; k < MAX_NB; k++) {
        float2 io0 = h2f2(p[k].x);   // (i,o)@d0
        float2 io1 = h2f2(p[k].y);   // (i,o)@d0+1
        float2 uf0 = h2f2(p[k].z);   // (u,f)@d0
        float2 uf1 = h2f2(p[k].w);   // (u,f)@d0+1
        si[0] += io0.x; so[0] += io0.y; su[0] += uf0.x; vf[0][k] = uf0.y;
        si[1] += io1.x; so[1] += io1.y; su[1] += uf1.x; vf[1][k] = uf1.y;
        vc[k] = h2f2(cw[k]);         // (c(d0), c(d0+1))
    }

    // unpack depth-invariant one-hot preacts (biases included)
    float2 pio0 = h2f2(pre.x);   // (pi,po)@d0
    float2 pio1 = h2f2(pre.y);   // (pi,po)@d0+1
    float2 puf0 = h2f2(pre.z);   // (pu,pf)@d0
    float2 puf1 = h2f2(pre.w);   // (pu,pf)@d0+1

    float h[2], c[2];
    #pragma unroll
    for (int q = 0; q < 2; q++) {
        float pi = q ? pio1.x : pio0.x;
        float po = q ? pio1.y : pio0.y;
        float pu = q ? puf1.x : puf0.x;
        float pf = q ? puf1.y : puf0.y;

        float i_g = sigfast(si[q] + pi);
        float o_g = sigfast(so[q] + po);
        float u_g = tanhfast(su[q] + pu);

        float c_acc = i_g * u_g;
        #pragma unroll
        for (int k = 0; k < MAX_NB; k++)
            c_acc += sigfast(vf[q][k] + pf) * (q ? vc[k].y : vc[k].x);

        h[q] = o_g * tanhfast(c_acc);
        c[q] = c_acc;
        if (e == 0) { h[q] = 0.f; c[q] = 0.f; }
    }

    c_new[e * 64 + dh] = f2h2(c[0], c[1]);
    store_h2(nxt, e, d0, h[0], h[1]);
}

// ---------------------------------------------------------------------------
// Final node projection: out = relu(Wt[nid] + bt + sum_k Ht[adj[n,k]])
// ---------------------------------------------------------------------------
__global__ __launch_bounds__(256) void k_final(
    const int* __restrict__ node_ids, const int* __restrict__ adj_list,
    const float* __restrict__ Wt, const float* __restrict__ bt,
    float* __restrict__ out)
{
    __shared__ int s_a[2 * MAX_NB];
    __shared__ int s_nid[2];

    const float* __restrict__ Ht = g_Ht;

    const int tid = threadIdx.x;
    const int n0  = blockIdx.x * 2;

    if (tid < 2 * MAX_NB) {
        s_a[tid] = adj_list[n0 * MAX_NB + tid];
    } else if (tid < 2 * MAX_NB + 2) {
        int n = tid - 2 * MAX_NB;
        s_nid[n] = node_ids[n0 + n];
    }
    __syncthreads();

    const int ln = tid >> 7;
    const int d  = tid & 127;
    const int n  = n0 + ln;

    float s = 0.f;
    #pragma unroll
    for (int k = 0; k < MAX_NB; k++)
        s += Ht[s_a[ln * MAX_NB + k] * EMB + d];

    float v = s + Wt[s_nid[ln] * EMB + d] + bt[d];
    v = fmaxf(v, 0.f);
    if (n == 0) v = 0.f;
    out[n * EMB + d] = v;
}

// ---------------------------------------------------------------------------
extern "C" void kernel_launch(void* const* d_in, const int* in_sizes, int n_in,
                              void* d_out, int out_size)
{
    const int*   node_ids  = (const int*)d_in[0];
    const int*   edge_src  = (const int*)d_in[1];
    const int*   edge_type = (const int*)d_in[2];
    const int*   adj_list  = (const int*)d_in[3];
    const int*   bond_list = (const int*)d_in[4];
    const float* Wi = (const float*)d_in[5];
    const float* bi = (const float*)d_in[6];
    const float* Wo = (const float*)d_in[7];
    const float* bo = (const float*)d_in[8];
    const float* Wf = (const float*)d_in[9];
    const float* bf = (const float*)d_in[10];
    const float* Wu = (const float*)d_in[11];
    const float* bu = (const float*)d_in[12];
    const float* Wt = (const float*)d_in[13];
    const float* bt = (const float*)d_in[14];
    float* out = (float*)d_out;

    cudaFuncSetAttribute(k_mma, cudaFuncAttributeMaxDynamicSharedMemorySize, MMA_SMEM);

    k_prep<<<5, 256>>>(Wi, Wo, Wu, Wf, Wt);
    k_pre0<<<(N_EDGES * 64) / 256, 256>>>(node_ids, edge_src, edge_type,
                                          Wi, bi, Wo, bo, Wu, bu, Wf, bf);

    int cur = 0, nxt = 1;
    for (int depth = 1; depth < 4; depth++) {
        k_mma<<<dim3(NT, 2), 256, MMA_SMEM>>>(cur, 0, 2);   // y=0: gates 0,1; y=1: gates 2,3
        k_update<<<N_EDGES / 4, 256>>>(cur, nxt, bond_list);
        int t = cur; cur = nxt; nxt = t;
    }

    k_mma<<<dim3(NT, 1), 256, MMA_SMEM>>>(cur, 4, 1);   // Ht -> g_Ht (fp32)
    k_final<<<N_NODES / 2, 256>>>(node_ids, adj_list, Wt, bt, out);
}